// round 17
// baseline (speedup 1.0000x reference)
#include <cuda_runtime.h>
#include <cuda_fp16.h>
#include <math.h>
#include <stdint.h>

#define NROWS 65536
#define DDIM  64
#define KCODES 512
#define COMMIT 0.25f
#define CROWS 64             // rows per CTA (4 warps x 16)
#define KCH   128            // codes per smem chunk

// ---------------- scratch (no allocations allowed) ----------------
__device__ float    g_wnorm[KCODES];            // 0.5*||w_k||^2
__device__ float    g_wT[KCODES * DDIM];        // w transposed [k][d] fp32
__device__ uint32_t g_whp[KCODES * DDIM / 2];   // w fp16, half2-packed [k][d/2]
__device__ int      g_counts[KCODES];
__device__ double   g_sumsq;

// ---------------- helpers ----------------
__device__ __forceinline__ unsigned int f2ord(float f) {
    unsigned int u = __float_as_uint(f);
    return (u & 0x80000000u) ? ~u : (u | 0x80000000u);
}
__device__ __forceinline__ void split16(float v, __half& hi, __half& lo) {
    hi = __float2half_rn(v);
    lo = __float2half_rn(v - __half2float(hi));
}
__device__ __forceinline__ uint32_t pkh2(__half a, __half b) {
    __half2 h = __halves2half2(a, b);
    return *(uint32_t*)&h;
}
// m16n8k16 row.col fp16 -> fp32 accumulate (legacy HMMA, portable PTX)
__device__ __forceinline__ void mma16816(float c[4], const uint32_t a[4],
                                         uint32_t b0, uint32_t b1) {
    asm("mma.sync.aligned.m16n8k16.row.col.f32.f16.f16.f32 "
        "{%0,%1,%2,%3}, {%4,%5,%6,%7}, {%8,%9}, {%0,%1,%2,%3};"
        : "+f"(c[0]), "+f"(c[1]), "+f"(c[2]), "+f"(c[3])
        : "r"(a[0]), "r"(a[1]), "r"(a[2]), "r"(a[3]), "r"(b0), "r"(b1));
}
__device__ __forceinline__ void top3upd(float& v1, int& k1, float& v2, int& k2,
                                        float& v3, int& k3, float s, int kk) {
    if (s > v1)      { v3 = v2; k3 = k2; v2 = v1; k2 = k1; v1 = s; k1 = kk; }
    else if (s > v2) { v3 = v2; k3 = k2; v2 = s; k2 = kk; }
    else if (s > v3) { v3 = s; k3 = kk; }
}

// ---------------- kernel 0: prep (wnorm, wT, fp16 pack, zero) --------------
__global__ void vq_prep_kernel(const float* __restrict__ w) {
    __shared__ float tile[16][65];
    const int tid = threadIdx.x, k0 = blockIdx.x * 16;   // 32 blocks x 256
    for (int i = tid; i < 16 * 64; i += 256) {
        int d = i >> 4, kl = i & 15;
        tile[kl][d] = w[d * KCODES + k0 + kl];
    }
    __syncthreads();
    if (tid < 16) {
        float s = 0.f;
        #pragma unroll
        for (int d = 0; d < 64; d++) { float v = tile[tid][d]; s += v * v; }
        g_wnorm[k0 + tid] = 0.5f * s;
    }
    for (int i = tid; i < 16 * 64; i += 256) {
        int kl = i >> 6, d = i & 63;
        g_wT[(k0 + kl) * DDIM + d] = tile[kl][d];
    }
    for (int i = tid; i < 16 * 32; i += 256) {
        int kl = i >> 5, dw = i & 31;
        g_whp[(k0 + kl) * 32 + dw] =
            pkh2(__float2half_rn(tile[kl][2 * dw]),
                 __float2half_rn(tile[kl][2 * dw + 1]));
    }
    if (blockIdx.x == 0) {
        for (int i = tid; i < KCODES; i += 256) g_counts[i] = 0;
        if (tid == 0) g_sumsq = 0.0;
    }
}

// ---------------- smem layout (dynamic) ----------------
#define XS_PITCH 68
#define SM_XS    0                                   // 64 x 68 f32 = 17408
#define SM_WH    17408                               // 128 x 72 half = 18432
#define SM_SWN   (SM_WH + 18432)                     // 512 f32 = 2048
#define SM_SK    (SM_SWN + 2048)                     // 64 int
#define SM_MAIN  (SM_SK + 256)

// ---------------- kernel 1: HMMA 2-term scoring + top3/rescore + gather ----
// 1024 CTAs x 128 thr. Warp w: rows w*16..w*16+15 (m16). Score ~= (xh+xl)·wh
// (x exact to 2^-22, w single fp16 -> score err std ~2.4e-4). Each quad-lane
// tracks its local top-3 of its 128 codes, rescores them exactly in fp32,
// then a quad shfl-max on exact keys picks the reference-faithful argmax.
__global__ __launch_bounds__(128) void vq_main_kernel(
    const float* __restrict__ x, float* __restrict__ out, int out_size)
{
    extern __shared__ unsigned char smraw[];
    float*  xs  = (float*)(smraw + SM_XS);           // [64][68]
    __half* whs = (__half*)(smraw + SM_WH);          // [128][72]
    float*  swn = (float*)(smraw + SM_SWN);
    int*    sk  = (int*)(smraw + SM_SK);

    const int tid  = threadIdx.x;
    const int lane = tid & 31, warp = tid >> 5;
    const int g = lane >> 2, tg = lane & 3;
    const int row0 = blockIdx.x * CROWS;
    const int rA = warp * 16 + g, rB = rA + 8;       // this thread's 2 rows

    // x tile -> smem (coalesced)
    for (int i = tid; i < CROWS * DDIM; i += 128) {
        int r = i >> 6, d = i & 63;
        xs[r * XS_PITCH + d] = x[(long long)(row0 + r) * DDIM + d];
    }
    for (int i = tid; i < KCODES; i += 128) swn[i] = g_wnorm[i];
    __syncthreads();

    // build A fragments (4 ksteps, hi+lo splits of x) from xs
    uint32_t ahi[4][4], alo[4][4];
    #pragma unroll
    for (int ks = 0; ks < 4; ks++) {
        #pragma unroll
        for (int q = 0; q < 4; q++) {              // q: {rA,c0},{rB,c0},{rA,c8},{rB,c8}
            int rr = (q & 1) ? rB : rA;
            int cc = ks * 16 + 2 * tg + ((q >> 1) << 3);
            float2 v = *(float2*)&xs[rr * XS_PITCH + cc];
            __half h0, l0, h1, l1;
            split16(v.x, h0, l0);
            split16(v.y, h1, l1);
            ahi[ks][q] = pkh2(h0, h1);
            alo[ks][q] = pkh2(l0, l1);
        }
    }

    float v1a = -INFINITY, v2a = -INFINITY, v3a = -INFINITY;
    float v1b = -INFINITY, v2b = -INFINITY, v3b = -INFINITY;
    int   k1a = 0, k2a = 0, k3a = 0, k1b = 0, k2b = 0, k3b = 0;

    for (int c = 0; c < 4; c++) {
        __syncthreads();
        // fill fp16 chunk (coalesced global, conflict-free smem)
        for (int i = tid; i < KCH * 32; i += 128) {
            int kl = i >> 5, dw = i & 31;
            *(uint32_t*)&whs[kl * 72 + dw * 2] = g_whp[(c * KCH + kl) * 32 + dw];
        }
        __syncthreads();

        for (int g8 = 0; g8 < 8; g8++) {
            const int lc = g8 * 16;                 // chunk-local code base
            float acc0[4] = {0.f, 0.f, 0.f, 0.f};
            float acc1[4] = {0.f, 0.f, 0.f, 0.f};
            #pragma unroll
            for (int ks = 0; ks < 4; ks++) {
                const int bo = (lc + g) * 72 + ks * 16 + 2 * tg;
                uint32_t b0h = *(uint32_t*)&whs[bo];
                uint32_t b1h = *(uint32_t*)&whs[bo + 8];
                uint32_t b0h2 = *(uint32_t*)&whs[bo + 8 * 72];
                uint32_t b1h2 = *(uint32_t*)&whs[bo + 8 * 72 + 8];
                mma16816(acc0, ahi[ks], b0h, b1h);
                mma16816(acc1, ahi[ks], b0h2, b1h2);
                mma16816(acc0, alo[ks], b0h, b1h);
                mma16816(acc1, alo[ks], b0h2, b1h2);
            }
            // epilogue: 2 subs x (2 rows x 2 codes), track lane-local top-3
            #pragma unroll
            for (int u = 0; u < 2; u++) {
                float* a = u ? acc1 : acc0;
                int cn = c * KCH + lc + u * 8 + 2 * tg;
                float s0 = a[0] - swn[cn];
                float s1 = a[1] - swn[cn + 1];
                float s2 = a[2] - swn[cn];
                float s3 = a[3] - swn[cn + 1];
                top3upd(v1a, k1a, v2a, k2a, v3a, k3a, s0, cn);
                top3upd(v1a, k1a, v2a, k2a, v3a, k3a, s1, cn + 1);
                top3upd(v1b, k1b, v2b, k2b, v3b, k3b, s2, cn);
                top3upd(v1b, k1b, v2b, k2b, v3b, k3b, s3, cn + 1);
            }
        }
    }

    const long long idx_off = (long long)NROWS * DDIM + 2;
    const bool write_q   = (out_size >= (long long)NROWS * DDIM);
    const bool write_idx = (out_size >= idx_off + NROWS);

    // exact fp32 rescore of each lane's 3 candidates, quad shfl-max on exact keys
    {
        const float4* xrA = (const float4*)&xs[rA * XS_PITCH];
        const float4* xrB = (const float4*)&xs[rB * XS_PITCH];
        int candA[3] = {k1a, k2a, k3a};
        int candB[3] = {k1b, k2b, k3b};
        unsigned long long keyA = 0ULL, keyB = 0ULL;
        #pragma unroll
        for (int t = 0; t < 3; t++) {
            const float4* wa = (const float4*)(g_wT + candA[t] * DDIM);
            const float4* wb = (const float4*)(g_wT + candB[t] * DDIM);
            float sa = 0.f, sb = 0.f;
            #pragma unroll
            for (int q = 0; q < 16; q++) {
                float4 xa = xrA[q], xb = xrB[q], a = wa[q], b = wb[q];
                sa += xa.x * a.x + xa.y * a.y + xa.z * a.z + xa.w * a.w;
                sb += xb.x * b.x + xb.y * b.y + xb.z * b.z + xb.w * b.w;
            }
            sa -= swn[candA[t]];
            sb -= swn[candB[t]];
            unsigned long long ka =
                ((unsigned long long)f2ord(sa) << 32) | (unsigned)(511 - candA[t]);
            unsigned long long kb =
                ((unsigned long long)f2ord(sb) << 32) | (unsigned)(511 - candB[t]);
            if (ka > keyA) keyA = ka;
            if (kb > keyB) keyB = kb;
        }
        #pragma unroll
        for (int off = 1; off <= 2; off <<= 1) {
            unsigned long long oa = __shfl_xor_sync(0xFFFFFFFFu, keyA, off);
            unsigned long long ob = __shfl_xor_sync(0xFFFFFFFFu, keyB, off);
            if (oa > keyA) keyA = oa;
            if (ob > keyB) keyB = ob;
        }
        if (tg == 0) {
            int kfA = 511 - (int)(keyA & 0xFFFFFFFFu);
            int kfB = 511 - (int)(keyB & 0xFFFFFFFFu);
            sk[rA] = kfA;
            sk[rB] = kfB;
            atomicAdd(&g_counts[kfA], 1);
            atomicAdd(&g_counts[kfB], 1);
            if (write_idx) {
                out[idx_off + row0 + rA] = (float)kfA;
                out[idx_off + row0 + rB] = (float)kfB;
            }
        }
    }
    __syncthreads();

    // fused gather: quantized out + squared error (x from smem)
    float partial = 0.f;
    if (write_q) {
        const int d = tid & 63, rh = tid >> 6;
        #pragma unroll 4
        for (int it = 0; it < CROWS / 2; it++) {
            int r = it * 2 + rh;
            int k = sk[r];
            float q  = g_wT[k * DDIM + d];
            float xv = xs[r * XS_PITCH + d];
            out[(long long)(row0 + r) * DDIM + d] = q;   // quantized_st == quantized
            float df = q - xv;
            partial += df * df;
        }
    }
    #pragma unroll
    for (int o = 16; o > 0; o >>= 1)
        partial += __shfl_down_sync(0xFFFFFFFFu, partial, o);
    if (lane == 0) atomicAdd(&g_sumsq, (double)partial);
}

// ---------------- kernel 2: loss + perplexity ----------------
__global__ void vq_final_kernel(float* __restrict__ out, int out_size) {
    __shared__ float red[512];
    int t = threadIdx.x;
    float p = (float)g_counts[t] * (1.0f / (float)NROWS);
    red[t] = p * logf(p + 1e-10f);
    __syncthreads();
    for (int s = 256; s > 0; s >>= 1) {
        if (t < s) red[t] += red[t + s];
        __syncthreads();
    }
    if (t == 0) {
        long long base = (long long)NROWS * DDIM;
        if (out_size >= base + 2) {
            double mse = g_sumsq / (double)((long long)NROWS * DDIM);
            out[base]     = (float)((1.0 + (double)COMMIT) * mse);
            out[base + 1] = expf(-red[0]);
        }
    }
}

// ---------------- launch ----------------
extern "C" void kernel_launch(void* const* d_in, const int* in_sizes, int n_in,
                              void* d_out, int out_size) {
    const float* x = (const float*)d_in[0];   // [65536, 64]
    const float* w = (const float*)d_in[1];   // [64, 512]
    float* out = (float*)d_out;

    cudaFuncSetAttribute(vq_main_kernel,
                         cudaFuncAttributeMaxDynamicSharedMemorySize, SM_MAIN);

    vq_prep_kernel<<<32, 256>>>(w);
    vq_main_kernel<<<NROWS / CROWS, 128, SM_MAIN>>>(x, out, out_size);
    vq_final_kernel<<<1, 512>>>(out, out_size);
}